// round 3
// baseline (speedup 1.0000x reference)
#include <cuda_runtime.h>
#include <math.h>
#include <stdint.h>

// ---------------------------------------------------------------------------
// Problem constants
// ---------------------------------------------------------------------------
#define EMBED  768
#define NWIN   200        // 8 batches * 5*5 windows
#define NTOK   196        // 14*14 tokens per window
#define NHEAD  12
#define HD     64
#define M_WIN  (NWIN*NTOK)   // 39200 window rows (includes padded tokens)
#define M_TOK  32768         // 8*64*64 real rows
#define FFDIM  3072
#define QKVN   2304

// ---------------------------------------------------------------------------
// Scratch (device globals: no allocation allowed in kernel_launch)
// ---------------------------------------------------------------------------
__device__ float g_hwin[(size_t)M_WIN * EMBED];   // LN1 + window partition  (120 MB)
__device__ float g_qkv [(size_t)M_WIN * QKVN];    // qkv projection          (361 MB)
__device__ float g_attn[(size_t)M_WIN * EMBED];   // attention output        (120 MB)
__device__ float g_x1  [(size_t)M_TOK * EMBED];   // x + attn residual       (100 MB)
__device__ float g_h2  [(size_t)M_TOK * EMBED];   // LN2 output              (100 MB)
__device__ float g_ff  [(size_t)M_TOK * FFDIM];   // gelu(fc1)               (402 MB)

// ---------------------------------------------------------------------------
// Helpers
// ---------------------------------------------------------------------------
__device__ __forceinline__ float gelu_f(float v) {
    // exact gelu (approximate=False): 0.5*x*(1+erf(x/sqrt(2)))
    return 0.5f * v * (1.0f + erff(v * 0.7071067811865476f));
}

// ---------------------------------------------------------------------------
// Kernel 1: LayerNorm(x) fused with window partition (zero padding)
// out rows: row = w*196 + t;  w = b*25 + wy*5 + wx;  t = p*14 + q
// ---------------------------------------------------------------------------
__global__ __launch_bounds__(256) void ln1_part_kernel(
    const float* __restrict__ x, const float* __restrict__ g,
    const float* __restrict__ b, float* __restrict__ outw)
{
    __shared__ float red[16];
    const int row = blockIdx.x;
    const int tid = threadIdx.x;
    const int t  = row % NTOK, wI = row / NTOK;
    const int bI = wI / 25,   wr = wI % 25;
    const int y  = (wr / 5) * 14 + t / 14;
    const int xx = (wr % 5) * 14 + t % 14;
    float* orow = outw + (size_t)row * EMBED;

    if (y >= 64 || xx >= 64) {                 // padded token -> zeros
        orow[tid] = 0.f; orow[tid + 256] = 0.f; orow[tid + 512] = 0.f;
        return;
    }
    const float* xr = x + (((size_t)bI * 64 + y) * 64 + xx) * EMBED;
    float v0 = xr[tid], v1 = xr[tid + 256], v2 = xr[tid + 512];
    float s  = v0 + v1 + v2;
    float s2 = v0 * v0 + v1 * v1 + v2 * v2;
    #pragma unroll
    for (int o = 16; o; o >>= 1) {
        s  += __shfl_xor_sync(0xffffffffu, s,  o);
        s2 += __shfl_xor_sync(0xffffffffu, s2, o);
    }
    if ((tid & 31) == 0) { red[tid >> 5] = s; red[8 + (tid >> 5)] = s2; }
    __syncthreads();
    float S = 0.f, S2 = 0.f;
    #pragma unroll
    for (int i = 0; i < 8; i++) { S += red[i]; S2 += red[8 + i]; }
    const float mean = S * (1.f / 768.f);
    const float rstd = rsqrtf(S2 * (1.f / 768.f) - mean * mean + 1e-6f);
    orow[tid]       = (v0 - mean) * rstd * g[tid]       + b[tid];
    orow[tid + 256] = (v1 - mean) * rstd * g[tid + 256] + b[tid + 256];
    orow[tid + 512] = (v2 - mean) * rstd * g[tid + 512] + b[tid + 512];
}

// ---------------------------------------------------------------------------
// Kernel: LayerNorm over contiguous rows (LN2)
// ---------------------------------------------------------------------------
__global__ __launch_bounds__(256) void ln2_kernel(
    const float* __restrict__ xin, const float* __restrict__ g,
    const float* __restrict__ b, float* __restrict__ outp)
{
    __shared__ float red[16];
    const int row = blockIdx.x;
    const int tid = threadIdx.x;
    const float* xr = xin + (size_t)row * EMBED;
    float* orow = outp + (size_t)row * EMBED;
    float v0 = xr[tid], v1 = xr[tid + 256], v2 = xr[tid + 512];
    float s  = v0 + v1 + v2;
    float s2 = v0 * v0 + v1 * v1 + v2 * v2;
    #pragma unroll
    for (int o = 16; o; o >>= 1) {
        s  += __shfl_xor_sync(0xffffffffu, s,  o);
        s2 += __shfl_xor_sync(0xffffffffu, s2, o);
    }
    if ((tid & 31) == 0) { red[tid >> 5] = s; red[8 + (tid >> 5)] = s2; }
    __syncthreads();
    float S = 0.f, S2 = 0.f;
    #pragma unroll
    for (int i = 0; i < 8; i++) { S += red[i]; S2 += red[8 + i]; }
    const float mean = S * (1.f / 768.f);
    const float rstd = rsqrtf(S2 * (1.f / 768.f) - mean * mean + 1e-6f);
    orow[tid]       = (v0 - mean) * rstd * g[tid]       + b[tid];
    orow[tid + 256] = (v1 - mean) * rstd * g[tid + 256] + b[tid + 256];
    orow[tid + 512] = (v2 - mean) * rstd * g[tid + 512] + b[tid + 512];
}

// ---------------------------------------------------------------------------
// SGEMM: C[M,N] = A[M,K] @ B[K,N] + bias, 128x128x16 tile, 8x8 per thread.
// Epilogues: 0=plain  1=gelu  2=residual add (res same layout)
//            3=window-unpartition scatter: x1[pos] = x[pos] + v (skip pads)
// N must be a multiple of 128 and K a multiple of 16 (true for all calls).
// ---------------------------------------------------------------------------
template<int EPI>
__global__ __launch_bounds__(256, 2) void sgemm(
    const float* __restrict__ A, const float* __restrict__ Bm,
    const float* __restrict__ bias, float* __restrict__ C,
    int M, int N, int K, const float* __restrict__ res)
{
    __shared__ float As[16][128];
    __shared__ float Bs[16][128];
    const int tid = threadIdx.x;
    const int bm = blockIdx.y * 128;
    const int bn = blockIdx.x * 128;
    const int tx = tid & 15, ty = tid >> 4;
    const int tm0 = ty * 8, tn0 = tx * 8;
    float acc[8][8];
    #pragma unroll
    for (int i = 0; i < 8; i++)
        #pragma unroll
        for (int j = 0; j < 8; j++) acc[i][j] = 0.f;

    for (int k0 = 0; k0 < K; k0 += 16) {
        #pragma unroll
        for (int s = 0; s < 2; s++) {          // A tile 128x16 (store transposed)
            int f = tid + s * 256;
            int r = f >> 2, c4 = (f & 3) << 2;
            int gm = bm + r;
            float4 v = make_float4(0.f, 0.f, 0.f, 0.f);
            if (gm < M) v = *(const float4*)(A + (size_t)gm * K + k0 + c4);
            As[c4 + 0][r] = v.x; As[c4 + 1][r] = v.y;
            As[c4 + 2][r] = v.z; As[c4 + 3][r] = v.w;
        }
        #pragma unroll
        for (int s = 0; s < 2; s++) {          // B tile 16x128
            int f = tid + s * 256;
            int r = f >> 5, c4 = (f & 31) << 2;
            *(float4*)&Bs[r][c4] = *(const float4*)(Bm + (size_t)(k0 + r) * N + bn + c4);
        }
        __syncthreads();
        #pragma unroll
        for (int kk = 0; kk < 16; kk++) {
            float ra[8], rb[8];
            *(float4*)(ra)     = *(const float4*)&As[kk][tm0];
            *(float4*)(ra + 4) = *(const float4*)&As[kk][tm0 + 4];
            *(float4*)(rb)     = *(const float4*)&Bs[kk][tn0];
            *(float4*)(rb + 4) = *(const float4*)&Bs[kk][tn0 + 4];
            #pragma unroll
            for (int i = 0; i < 8; i++)
                #pragma unroll
                for (int j = 0; j < 8; j++) acc[i][j] += ra[i] * rb[j];
        }
        __syncthreads();
    }

    #pragma unroll
    for (int i = 0; i < 8; i++) {
        const int m = bm + tm0 + i;
        if (m >= M) continue;
        size_t spos = 0;
        if (EPI == 3) {
            const int wI = m / NTOK, t = m % NTOK;
            const int bI = wI / 25, wr = wI % 25;
            const int y  = (wr / 5) * 14 + t / 14;
            const int xx = (wr % 5) * 14 + t % 14;
            if (y >= 64 || xx >= 64) continue;      // padded token: discard
            spos = (((size_t)bI * 64 + y) * 64 + xx) * EMBED;
        }
        #pragma unroll
        for (int j = 0; j < 8; j++) {
            const int n = bn + tn0 + j;
            float v = acc[i][j] + bias[n];
            if (EPI == 0)      C[(size_t)m * N + n] = v;
            else if (EPI == 1) C[(size_t)m * N + n] = gelu_f(v);
            else if (EPI == 2) C[(size_t)m * N + n] = res[(size_t)m * N + n] + v;
            else               C[spos + n] = res[spos + n] + v;
        }
    }
}

// ---------------------------------------------------------------------------
// Attention: one block per (window, head). Q/K/V + rel-pos tables in smem.
// score(i,j) = SCALE*dot(q_i,k_j) + dot(q_i, Rh[p_i-jp+13]) + dot(q_i, Rw[q_i-jq+13])
// Softmax over all 196 keys (padding tokens participate, per reference).
// 2 queries per warp-pass; padded strides for conflict-free smem access.
// ---------------------------------------------------------------------------
#define ATTN_SMEM_FLOATS (NTOK*68 + NTOK*68 + NTOK*64 + 27*64 + 27*64 + NTOK*14 + NTOK*14 + 8*2*NTOK)
#define ATTN_SMEM_BYTES  (ATTN_SMEM_FLOATS * 4)

__global__ __launch_bounds__(256) void attn_kernel(
    const float* __restrict__ qkv, const float* __restrict__ relh,
    const float* __restrict__ relw, float* __restrict__ ao)
{
    extern __shared__ float sm[];
    float* Qs  = sm;                    // [196][68]
    float* Ks  = Qs  + NTOK * 68;       // [196][68]
    float* Vs  = Ks  + NTOK * 68;       // [196][64]
    float* Rh  = Vs  + NTOK * 64;       // [27][64]
    float* Rw  = Rh  + 27 * 64;         // [27][64]
    float* BHs = Rw  + 27 * 64;         // [196][14]
    float* BWs = BHs + NTOK * 14;       // [196][14]
    float* Ps  = BWs + NTOK * 14;       // [8 warps][2][196]

    const int tid = threadIdx.x;
    const int w = blockIdx.x / NHEAD, h = blockIdx.x % NHEAD;
    const float* base = qkv + (size_t)w * NTOK * QKVN + h * HD;

    // --- load Q, K, V tiles ---
    for (int idx = tid; idx < NTOK * 16; idx += 256) {
        const int t = idx >> 4, c4 = (idx & 15) << 2;
        const float* rp = base + (size_t)t * QKVN;
        float4 q4 = *(const float4*)(rp + c4);
        float4 k4 = *(const float4*)(rp + 768 + c4);
        float4 v4 = *(const float4*)(rp + 1536 + c4);
        *(float4*)&Qs[t * 68 + c4] = q4;
        *(float4*)&Ks[t * 68 + c4] = k4;
        *(float4*)&Vs[t * 64 + c4] = v4;
    }
    for (int idx = tid; idx < 27 * 64; idx += 256) {
        Rh[idx] = relh[idx];
        Rw[idx] = relw[idx];
    }
    __syncthreads();

    const int wid = tid >> 5, lane = tid & 31;

    // --- decomposed rel-pos bias: one warp per query, lanes split head-dim ---
    for (int i = wid; i < NTOK; i += 8) {
        const int p = i / 14, qc = i % 14;
        const float2 q2 = *(const float2*)&Qs[i * 68 + 2 * lane];
        float acch[14], accw[14];
        #pragma unroll
        for (int r = 0; r < 14; r++) {
            const float2 rh2 = *(const float2*)&Rh[(p  + 13 - r) * 64 + 2 * lane];
            const float2 rw2 = *(const float2*)&Rw[(qc + 13 - r) * 64 + 2 * lane];
            acch[r] = q2.x * rh2.x + q2.y * rh2.y;
            accw[r] = q2.x * rw2.x + q2.y * rw2.y;
        }
        #pragma unroll
        for (int o = 16; o; o >>= 1) {
            #pragma unroll
            for (int r = 0; r < 14; r++) {
                acch[r] += __shfl_xor_sync(0xffffffffu, acch[r], o);
                accw[r] += __shfl_xor_sync(0xffffffffu, accw[r], o);
            }
        }
        if (lane == 0) {
            #pragma unroll
            for (int r = 0; r < 14; r++) { BHs[i * 14 + r] = acch[r]; BWs[i * 14 + r] = accw[r]; }
        }
    }
    __syncthreads();

    const float SCALE = 0.125f;    // 64^-0.5
    float* P0 = Ps + wid * (2 * NTOK);
    float* P1 = P0 + NTOK;

    // --- scores + softmax + AV: 2 queries per warp-pass ---
    for (int i0 = wid * 2; i0 < NTOK; i0 += 16) {
        const int i1 = i0 + 1;
        const float* q0p = &Qs[i0 * 68];
        const float* q1p = &Qs[i1 * 68];
        float s0[7], s1[7];
        float mx0 = -1e30f, mx1 = -1e30f;
        #pragma unroll
        for (int jj = 0; jj < 7; jj++) {
            const int j = jj * 32 + lane;
            float a0 = -1e30f, a1 = -1e30f;
            if (j < NTOK) {
                const float* kr = &Ks[j * 68];
                float d0 = 0.f, d1 = 0.f;
                #pragma unroll
                for (int d = 0; d < 64; d += 4) {
                    float4 k4 = *(const float4*)(kr + d);
                    float4 qa = *(const float4*)(q0p + d);
                    float4 qb = *(const float4*)(q1p + d);
                    d0 += qa.x * k4.x + qa.y * k4.y + qa.z * k4.z + qa.w * k4.w;
                    d1 += qb.x * k4.x + qb.y * k4.y + qb.z * k4.z + qb.w * k4.w;
                }
                const int jp = j / 14, jq = j % 14;
                a0 = d0 * SCALE + BHs[i0 * 14 + jp] + BWs[i0 * 14 + jq];
                a1 = d1 * SCALE + BHs[i1 * 14 + jp] + BWs[i1 * 14 + jq];
            }
            s0[jj] = a0; s1[jj] = a1;
            mx0 = fmaxf(mx0, a0); mx1 = fmaxf(mx1, a1);
        }
        #pragma unroll
        for (int o = 16; o; o >>= 1) {
            mx0 = fmaxf(mx0, __shfl_xor_sync(0xffffffffu, mx0, o));
            mx1 = fmaxf(mx1, __shfl_xor_sync(0xffffffffu, mx1, o));
        }
        float sum0 = 0.f, sum1 = 0.f;
        #pragma unroll
        for (int jj = 0; jj < 7; jj++) {
            float e0 = __expf(s0[jj] - mx0);
            float e1 = __expf(s1[jj] - mx1);
            if (jj * 32 + lane >= NTOK) { e0 = 0.f; e1 = 0.f; }
            s0[jj] = e0; s1[jj] = e1;
            sum0 += e0; sum1 += e1;
        }
        #pragma unroll
        for (int o = 16; o; o >>= 1) {
            sum0 += __shfl_xor_sync(0xffffffffu, sum0, o);
            sum1 += __shfl_xor_sync(0xffffffffu, sum1, o);
        }
        const float r0 = 1.f / sum0, r1 = 1.f / sum1;
        #pragma unroll
        for (int jj = 0; jj < 7; jj++) {
            const int j = jj * 32 + lane;
            if (j < NTOK) { P0[j] = s0[jj] * r0; P1[j] = s1[jj] * r1; }
        }
        __syncwarp();
        float o00 = 0.f, o01 = 0.f, o10 = 0.f, o11 = 0.f;   // [query][d-pair]
        #pragma unroll 7
        for (int j4 = 0; j4 < 49; j4++) {
            const float4 p0 = *(const float4*)(P0 + j4 * 4);
            const float4 p1 = *(const float4*)(P1 + j4 * 4);
            const float* vb = &Vs[j4 * 4 * 64 + 2 * lane];
            const float2 v0 = *(const float2*)(vb);
            const float2 v1 = *(const float2*)(vb + 64);
            const float2 v2 = *(const float2*)(vb + 128);
            const float2 v3 = *(const float2*)(vb + 192);
            o00 += p0.x * v0.x + p0.y * v1.x + p0.z * v2.x + p0.w * v3.x;
            o01 += p0.x * v0.y + p0.y * v1.y + p0.z * v2.y + p0.w * v3.y;
            o10 += p1.x * v0.x + p1.y * v1.x + p1.z * v2.x + p1.w * v3.x;
            o11 += p1.x * v0.y + p1.y * v1.y + p1.z * v2.y + p1.w * v3.y;
        }
        float* orow0 = ao + (size_t)(w * NTOK + i0) * EMBED + h * HD + 2 * lane;
        float* orow1 = ao + (size_t)(w * NTOK + i1) * EMBED + h * HD + 2 * lane;
        *(float2*)orow0 = make_float2(o00, o01);
        *(float2*)orow1 = make_float2(o10, o11);
        __syncwarp();
    }
}

// ---------------------------------------------------------------------------
// kernel_launch
// ---------------------------------------------------------------------------
extern "C" void kernel_launch(void* const* d_in, const int* in_sizes, int n_in,
                              void* d_out, int out_size)
{
    const float* x      = (const float*)d_in[0];
    const float* g1     = (const float*)d_in[1];
    const float* beta1  = (const float*)d_in[2];
    const float* w_qkv  = (const float*)d_in[3];
    const float* b_qkv  = (const float*)d_in[4];
    const float* w_proj = (const float*)d_in[5];
    const float* b_proj = (const float*)d_in[6];
    const float* relh   = (const float*)d_in[7];
    const float* relw   = (const float*)d_in[8];
    const float* g2     = (const float*)d_in[9];
    const float* beta2  = (const float*)d_in[10];
    const float* w_fc1  = (const float*)d_in[11];
    const float* b_fc1  = (const float*)d_in[12];
    const float* w_fc2  = (const float*)d_in[13];
    const float* b_fc2  = (const float*)d_in[14];
    float* out = (float*)d_out;

    float *p_hwin, *p_qkv, *p_attn, *p_x1, *p_h2, *p_ff;
    cudaGetSymbolAddress((void**)&p_hwin, g_hwin);
    cudaGetSymbolAddress((void**)&p_qkv,  g_qkv);
    cudaGetSymbolAddress((void**)&p_attn, g_attn);
    cudaGetSymbolAddress((void**)&p_x1,   g_x1);
    cudaGetSymbolAddress((void**)&p_h2,   g_h2);
    cudaGetSymbolAddress((void**)&p_ff,   g_ff);

    cudaFuncSetAttribute(attn_kernel, cudaFuncAttributeMaxDynamicSharedMemorySize,
                         ATTN_SMEM_BYTES);

    // 1. LN1 + window partition (padded tokens zeroed)
    ln1_part_kernel<<<M_WIN, 256>>>(x, g1, beta1, p_hwin);

    // 2. QKV projection: (39200,768) @ (768,2304) + bias
    sgemm<0><<<dim3(QKVN / 128, (M_WIN + 127) / 128), 256>>>(
        p_hwin, w_qkv, b_qkv, p_qkv, M_WIN, QKVN, EMBED, nullptr);

    // 3. Window attention with decomposed rel-pos bias
    attn_kernel<<<NWIN * NHEAD, 256, ATTN_SMEM_BYTES>>>(p_qkv, relh, relw, p_attn);

    // 4. Output projection + window unpartition + residual: x1 = x + proj(attn)
    sgemm<3><<<dim3(EMBED / 128, (M_WIN + 127) / 128), 256>>>(
        p_attn, w_proj, b_proj, p_x1, M_WIN, EMBED, EMBED, x);

    // 5. LN2
    ln2_kernel<<<M_TOK, 256>>>(p_x1, g2, beta2, p_h2);

    // 6. fc1 + exact GELU
    sgemm<1><<<dim3(FFDIM / 128, M_TOK / 128), 256>>>(
        p_h2, w_fc1, b_fc1, p_ff, M_TOK, FFDIM, EMBED, nullptr);

    // 7. fc2 + residual -> final output
    sgemm<2><<<dim3(EMBED / 128, M_TOK / 128), 256>>>(
        p_ff, w_fc2, b_fc2, out, M_TOK, EMBED, FFDIM, p_x1);
}

// round 6
// speedup vs baseline: 2.1829x; 2.1829x over previous
#include <cuda_runtime.h>
#include <cuda_bf16.h>
#include <math.h>
#include <stdint.h>

// ---------------------------------------------------------------------------
// Problem constants
// ---------------------------------------------------------------------------
#define EMBED  768
#define NWIN   200
#define NTOK   196
#define NHEAD  12
#define HD     64
#define M_WIN  (NWIN*NTOK)   // 39200
#define M_TOK  32768
#define FFDIM  3072
#define QKVN   2304

// ---------------------------------------------------------------------------
// Scratch (device globals; no allocation allowed)
// ---------------------------------------------------------------------------
__device__ __nv_bfloat16 g_hwin_hi[(size_t)M_WIN*EMBED];
__device__ __nv_bfloat16 g_hwin_lo[(size_t)M_WIN*EMBED];
__device__ float         g_qkv   [(size_t)M_WIN*QKVN];
__device__ __nv_bfloat16 g_attn_hi[(size_t)M_WIN*EMBED];
__device__ __nv_bfloat16 g_attn_lo[(size_t)M_WIN*EMBED];
__device__ float         g_x1    [(size_t)M_TOK*EMBED];
__device__ __nv_bfloat16 g_h2_hi [(size_t)M_TOK*EMBED];
__device__ __nv_bfloat16 g_h2_lo [(size_t)M_TOK*EMBED];
__device__ __nv_bfloat16 g_ff_hi [(size_t)M_TOK*FFDIM];
__device__ __nv_bfloat16 g_ff_lo [(size_t)M_TOK*FFDIM];
// transposed split weights: [N][K]
__device__ __nv_bfloat16 g_wqkv_hi[(size_t)QKVN*EMBED];
__device__ __nv_bfloat16 g_wqkv_lo[(size_t)QKVN*EMBED];
__device__ __nv_bfloat16 g_wprj_hi[(size_t)EMBED*EMBED];
__device__ __nv_bfloat16 g_wprj_lo[(size_t)EMBED*EMBED];
__device__ __nv_bfloat16 g_wfc1_hi[(size_t)FFDIM*EMBED];
__device__ __nv_bfloat16 g_wfc1_lo[(size_t)FFDIM*EMBED];
__device__ __nv_bfloat16 g_wfc2_hi[(size_t)EMBED*FFDIM];
__device__ __nv_bfloat16 g_wfc2_lo[(size_t)EMBED*FFDIM];

// ---------------------------------------------------------------------------
// Helpers
// ---------------------------------------------------------------------------
__device__ __forceinline__ float gelu_f(float v) {
    return 0.5f * v * (1.0f + erff(v * 0.7071067811865476f));
}
__device__ __forceinline__ void split2(float v, __nv_bfloat16& h, __nv_bfloat16& l) {
    h = __float2bfloat16(v);
    l = __float2bfloat16(v - __bfloat162float(h));
}
__device__ __forceinline__ uint32_t s2u(const void* p) {
    uint32_t a;
    asm("{ .reg .u64 t; cvta.to.shared.u64 t, %1; cvt.u32.u64 %0, t; }" : "=r"(a) : "l"(p));
    return a;
}
__device__ __forceinline__ void ldsm_x4(uint32_t& r0, uint32_t& r1, uint32_t& r2,
                                        uint32_t& r3, uint32_t addr) {
    asm volatile("ldmatrix.sync.aligned.m8n8.x4.shared.b16 {%0,%1,%2,%3}, [%4];"
                 : "=r"(r0), "=r"(r1), "=r"(r2), "=r"(r3) : "r"(addr));
}
__device__ __forceinline__ void mma16816(float* c, uint32_t a0, uint32_t a1,
                                         uint32_t a2, uint32_t a3,
                                         uint32_t b0, uint32_t b1) {
    asm volatile(
        "mma.sync.aligned.m16n8k16.row.col.f32.bf16.bf16.f32 "
        "{%0,%1,%2,%3}, {%4,%5,%6,%7}, {%8,%9}, {%0,%1,%2,%3};"
        : "+f"(c[0]), "+f"(c[1]), "+f"(c[2]), "+f"(c[3])
        : "r"(a0), "r"(a1), "r"(a2), "r"(a3), "r"(b0), "r"(b1));
}
__device__ __forceinline__ void cp16(uint32_t saddr, const void* g) {
    asm volatile("cp.async.cg.shared.global [%0], [%1], 16;" :: "r"(saddr), "l"(g));
}
__device__ __forceinline__ void cp_commit() {
    asm volatile("cp.async.commit_group;");
}

// ---------------------------------------------------------------------------
// Weight prep: transpose [K,N] fp32 -> [N,K] bf16 hi/lo
// ---------------------------------------------------------------------------
__global__ __launch_bounds__(256) void wprep(
    const float* __restrict__ W, __nv_bfloat16* __restrict__ Th,
    __nv_bfloat16* __restrict__ Tl, int K, int N)
{
    __shared__ float t[32][33];
    const int n0 = blockIdx.x * 32, k0 = blockIdx.y * 32;
    const int tx = threadIdx.x & 31, ty = threadIdx.x >> 5;
    #pragma unroll
    for (int i = 0; i < 32; i += 8)
        t[ty + i][tx] = W[(size_t)(k0 + ty + i) * N + n0 + tx];
    __syncthreads();
    #pragma unroll
    for (int i = 0; i < 32; i += 8) {
        float v = t[tx][ty + i];
        __nv_bfloat16 h, l; split2(v, h, l);
        size_t o = (size_t)(n0 + ty + i) * K + k0 + tx;
        Th[o] = h; Tl[o] = l;
    }
}

// ---------------------------------------------------------------------------
// LN1 + window partition -> split bf16
// ---------------------------------------------------------------------------
__global__ __launch_bounds__(256) void ln1_part_kernel(
    const float* __restrict__ x, const float* __restrict__ g,
    const float* __restrict__ b, __nv_bfloat16* __restrict__ ohi,
    __nv_bfloat16* __restrict__ olo)
{
    __shared__ float red[16];
    const int row = blockIdx.x, tid = threadIdx.x;
    const int t = row % NTOK, wI = row / NTOK;
    const int bI = wI / 25, wr = wI % 25;
    const int y  = (wr / 5) * 14 + t / 14;
    const int xx = (wr % 5) * 14 + t % 14;
    const size_t ro = (size_t)row * EMBED;
    if (y >= 64 || xx >= 64) {
        const __nv_bfloat16 z = __float2bfloat16(0.f);
        ohi[ro+tid]=z; ohi[ro+tid+256]=z; ohi[ro+tid+512]=z;
        olo[ro+tid]=z; olo[ro+tid+256]=z; olo[ro+tid+512]=z;
        return;
    }
    const float* xr = x + (((size_t)bI * 64 + y) * 64 + xx) * EMBED;
    float v0 = xr[tid], v1 = xr[tid+256], v2 = xr[tid+512];
    float s = v0+v1+v2, s2 = v0*v0+v1*v1+v2*v2;
    #pragma unroll
    for (int o = 16; o; o >>= 1) {
        s  += __shfl_xor_sync(0xffffffffu, s,  o);
        s2 += __shfl_xor_sync(0xffffffffu, s2, o);
    }
    if ((tid & 31) == 0) { red[tid>>5] = s; red[8+(tid>>5)] = s2; }
    __syncthreads();
    float S=0.f, S2=0.f;
    #pragma unroll
    for (int i = 0; i < 8; i++) { S += red[i]; S2 += red[8+i]; }
    const float mean = S * (1.f/768.f);
    const float rstd = rsqrtf(S2*(1.f/768.f) - mean*mean + 1e-6f);
    __nv_bfloat16 h, l;
    float o0 = (v0-mean)*rstd*g[tid]     + b[tid];
    float o1 = (v1-mean)*rstd*g[tid+256] + b[tid+256];
    float o2 = (v2-mean)*rstd*g[tid+512] + b[tid+512];
    split2(o0,h,l); ohi[ro+tid]=h;     olo[ro+tid]=l;
    split2(o1,h,l); ohi[ro+tid+256]=h; olo[ro+tid+256]=l;
    split2(o2,h,l); ohi[ro+tid+512]=h; olo[ro+tid+512]=l;
}

// ---------------------------------------------------------------------------
// LN2 -> split bf16
// ---------------------------------------------------------------------------
__global__ __launch_bounds__(256) void ln2_kernel(
    const float* __restrict__ xin, const float* __restrict__ g,
    const float* __restrict__ b, __nv_bfloat16* __restrict__ ohi,
    __nv_bfloat16* __restrict__ olo)
{
    __shared__ float red[16];
    const int row = blockIdx.x, tid = threadIdx.x;
    const float* xr = xin + (size_t)row * EMBED;
    const size_t ro = (size_t)row * EMBED;
    float v0 = xr[tid], v1 = xr[tid+256], v2 = xr[tid+512];
    float s = v0+v1+v2, s2 = v0*v0+v1*v1+v2*v2;
    #pragma unroll
    for (int o = 16; o; o >>= 1) {
        s  += __shfl_xor_sync(0xffffffffu, s,  o);
        s2 += __shfl_xor_sync(0xffffffffu, s2, o);
    }
    if ((tid & 31) == 0) { red[tid>>5] = s; red[8+(tid>>5)] = s2; }
    __syncthreads();
    float S=0.f, S2=0.f;
    #pragma unroll
    for (int i = 0; i < 8; i++) { S += red[i]; S2 += red[8+i]; }
    const float mean = S * (1.f/768.f);
    const float rstd = rsqrtf(S2*(1.f/768.f) - mean*mean + 1e-6f);
    __nv_bfloat16 h, l;
    float o0 = (v0-mean)*rstd*g[tid]     + b[tid];
    float o1 = (v1-mean)*rstd*g[tid+256] + b[tid+256];
    float o2 = (v2-mean)*rstd*g[tid+512] + b[tid+512];
    split2(o0,h,l); ohi[ro+tid]=h;     olo[ro+tid]=l;
    split2(o1,h,l); ohi[ro+tid+256]=h; olo[ro+tid+256]=l;
    split2(o2,h,l); ohi[ro+tid+512]=h; olo[ro+tid+512]=l;
}

// ---------------------------------------------------------------------------
// HMMA GEMM via mma.sync: C[M,N] = A[M,K] @ B[N,K]^T (+bias), 3-term bf16.
// CTA 128x128, 8 warps of 64x32, K-chunk 32, double-buffered cp.async smem.
// smem rows padded to 40 bf16 (80B) -> conflict-free ldmatrix.
// EPI: 0 bias->fp32 | 1 bias+gelu->bf16 splits | 2 bias+res->fp32
//      3 bias+window-scatter+res->fp32
// ---------------------------------------------------------------------------
#define LDA        40                      // bf16 per smem row
#define ARR_BYTES  (128*LDA*2)             // 10240 B per array
#define BUF_BYTES  (4*ARR_BYTES)           // Ah, Al, Bh, Bl
#define GSM_BYTES  (2*BUF_BYTES)           // 81920 B

template<int EPI>
__global__ __launch_bounds__(256, 2) void tgemm(
    const __nv_bfloat16* __restrict__ Ah, const __nv_bfloat16* __restrict__ Al,
    const __nv_bfloat16* __restrict__ Bh, const __nv_bfloat16* __restrict__ Bl,
    const float* __restrict__ bias, float* __restrict__ Co,
    __nv_bfloat16* __restrict__ Chi, __nv_bfloat16* __restrict__ Clo,
    int M, int N, int K, const float* __restrict__ res)
{
    extern __shared__ char smc[];
    const uint32_t smb = s2u(smc);
    const int tid = threadIdx.x;
    const int wid = tid >> 5, lane = tid & 31;
    const int bm = blockIdx.y * 128, bn = blockIdx.x * 128;
    const int wm = wid & 1, wn = wid >> 1;      // warp tile: 64 (M) x 32 (N)
    const int NC = K >> 5;                       // K-chunks of 32

    float acc[4][4][4];
    #pragma unroll
    for (int i = 0; i < 4; i++)
        #pragma unroll
        for (int j = 0; j < 4; j++)
            #pragma unroll
            for (int k = 0; k < 4; k++) acc[i][j][k] = 0.f;

    // per-thread ldmatrix byte offsets (within an array)
    const uint32_t offA = (uint32_t)((wm*64 + (lane & 7) + 8*((lane >> 3) & 1)) * LDA
                                     + 8*(lane >> 4)) * 2;
    const uint32_t offB = (uint32_t)((wn*32 + (lane & 7) + 8*(lane >> 4)) * LDA
                                     + 8*((lane >> 3) & 1)) * 2;

    auto load_chunk = [&](int c, int b) {
        const int k0 = c << 5;
        const uint32_t bb = smb + b * BUF_BYTES;
        #pragma unroll
        for (int a = 0; a < 4; a++) {
            const __nv_bfloat16* G = (a == 0) ? Ah : (a == 1) ? Al : (a == 2) ? Bh : Bl;
            const bool isA = (a < 2);
            const uint32_t ab = bb + a * ARR_BYTES;
            #pragma unroll
            for (int s = 0; s < 2; s++) {
                const int u = tid + s * 256;          // [0,512)
                const int row = u >> 2, seg = u & 3;
                int gr = (isA ? bm : bn) + row;
                if (isA && gr >= M) gr = M - 1;        // clamp (masked in epilogue)
                cp16(ab + (uint32_t)(row * LDA + seg * 8) * 2,
                     G + (size_t)gr * K + k0 + seg * 8);
            }
        }
        cp_commit();
    };

    load_chunk(0, 0);

    for (int c = 0; c < NC; c++) {
        const int b = c & 1;
        if (c + 1 < NC) {
            load_chunk(c + 1, b ^ 1);
            asm volatile("cp.async.wait_group 1;");
        } else {
            asm volatile("cp.async.wait_group 0;");
        }
        __syncthreads();

        const uint32_t bb = smb + b * BUF_BYTES;
        const uint32_t pAh = bb + offA;
        const uint32_t pAl = bb + ARR_BYTES + offA;
        const uint32_t pBh = bb + 2*ARR_BYTES + offB;
        const uint32_t pBl = bb + 3*ARR_BYTES + offB;

        #pragma unroll
        for (int ks = 0; ks < 2; ks++) {
            const uint32_t kso = ks * 32;             // 16 bf16 = 32 bytes
            uint32_t ah[4][4], bh[4][2], bl[4][2];
            #pragma unroll
            for (int mt = 0; mt < 4; mt++)
                ldsm_x4(ah[mt][0], ah[mt][1], ah[mt][2], ah[mt][3],
                        pAh + kso + mt * (16*LDA*2));
            #pragma unroll
            for (int L = 0; L < 2; L++) {
                ldsm_x4(bh[2*L][0], bh[2*L][1], bh[2*L+1][0], bh[2*L+1][1],
                        pBh + kso + L * (16*LDA*2));
                ldsm_x4(bl[2*L][0], bl[2*L][1], bl[2*L+1][0], bl[2*L+1][1],
                        pBl + kso + L * (16*LDA*2));
            }
            #pragma unroll
            for (int mt = 0; mt < 4; mt++)
                #pragma unroll
                for (int nt = 0; nt < 4; nt++)
                    mma16816(acc[mt][nt], ah[mt][0], ah[mt][1], ah[mt][2], ah[mt][3],
                             bh[nt][0], bh[nt][1]);
            #pragma unroll
            for (int mt = 0; mt < 4; mt++)
                #pragma unroll
                for (int nt = 0; nt < 4; nt++)
                    mma16816(acc[mt][nt], ah[mt][0], ah[mt][1], ah[mt][2], ah[mt][3],
                             bl[nt][0], bl[nt][1]);
            uint32_t al[4][4];
            #pragma unroll
            for (int mt = 0; mt < 4; mt++)
                ldsm_x4(al[mt][0], al[mt][1], al[mt][2], al[mt][3],
                        pAl + kso + mt * (16*LDA*2));
            #pragma unroll
            for (int mt = 0; mt < 4; mt++)
                #pragma unroll
                for (int nt = 0; nt < 4; nt++)
                    mma16816(acc[mt][nt], al[mt][0], al[mt][1], al[mt][2], al[mt][3],
                             bh[nt][0], bh[nt][1]);
        }
        __syncthreads();
    }

    // -------- epilogue (registers -> global) --------
    const int rbase = bm + wm*64;
    const int nbase = bn + wn*32;
    #pragma unroll
    for (int mt = 0; mt < 4; mt++) {
        #pragma unroll
        for (int half = 0; half < 2; half++) {
            const int m = rbase + mt*16 + (lane >> 2) + half*8;
            bool valid = (m < M);
            size_t spos = 0;
            if (EPI == 3 && valid) {
                const int wI = m / NTOK, t = m % NTOK;
                const int bI = wI / 25, wr = wI % 25;
                const int y  = (wr / 5) * 14 + t / 14;
                const int xx = (wr % 5) * 14 + t % 14;
                if (y >= 64 || xx >= 64) valid = false;
                else spos = (((size_t)bI * 64 + y) * 64 + xx) * EMBED;
            }
            if (!valid) continue;
            #pragma unroll
            for (int nt = 0; nt < 4; nt++) {
                const int n = nbase + nt*8 + (lane & 3)*2;
                float v0 = acc[mt][nt][half*2 + 0] + bias[n];
                float v1 = acc[mt][nt][half*2 + 1] + bias[n + 1];
                if (EPI == 0) {
                    *(float2*)(Co + (size_t)m * N + n) = make_float2(v0, v1);
                } else if (EPI == 1) {
                    v0 = gelu_f(v0); v1 = gelu_f(v1);
                    __nv_bfloat162 H, L;
                    split2(v0, H.x, L.x); split2(v1, H.y, L.y);
                    *(__nv_bfloat162*)(Chi + (size_t)m * N + n) = H;
                    *(__nv_bfloat162*)(Clo + (size_t)m * N + n) = L;
                } else if (EPI == 2) {
                    const float2 r2 = *(const float2*)(res + (size_t)m * N + n);
                    *(float2*)(Co + (size_t)m * N + n) = make_float2(v0 + r2.x, v1 + r2.y);
                } else {
                    const float2 r2 = *(const float2*)(res + spos + n);
                    *(float2*)(Co + spos + n) = make_float2(v0 + r2.x, v1 + r2.y);
                }
            }
        }
    }
}

// ---------------------------------------------------------------------------
// Window attention (fp32 in smem), outputs split bf16
// ---------------------------------------------------------------------------
#define ATTN_SMEM_FLOATS (NTOK*68 + NTOK*68 + NTOK*64 + 27*64 + 27*64 + NTOK*14 + NTOK*14 + 8*2*NTOK)
#define ATTN_SMEM_BYTES  (ATTN_SMEM_FLOATS * 4)

__global__ __launch_bounds__(256) void attn_kernel(
    const float* __restrict__ qkv, const float* __restrict__ relh,
    const float* __restrict__ relw, __nv_bfloat16* __restrict__ aohi,
    __nv_bfloat16* __restrict__ aolo)
{
    extern __shared__ float sm[];
    float* Qs  = sm;
    float* Ks  = Qs  + NTOK * 68;
    float* Vs  = Ks  + NTOK * 68;
    float* Rh  = Vs  + NTOK * 64;
    float* Rw  = Rh  + 27 * 64;
    float* BHs = Rw  + 27 * 64;
    float* BWs = BHs + NTOK * 14;
    float* Ps  = BWs + NTOK * 14;

    const int tid = threadIdx.x;
    const int w = blockIdx.x / NHEAD, h = blockIdx.x % NHEAD;
    const float* base = qkv + (size_t)w * NTOK * QKVN + h * HD;

    for (int idx = tid; idx < NTOK * 16; idx += 256) {
        const int t = idx >> 4, c4 = (idx & 15) << 2;
        const float* rp = base + (size_t)t * QKVN;
        float4 q4 = *(const float4*)(rp + c4);
        float4 k4 = *(const float4*)(rp + 768 + c4);
        float4 v4 = *(const float4*)(rp + 1536 + c4);
        *(float4*)&Qs[t * 68 + c4] = q4;
        *(float4*)&Ks[t * 68 + c4] = k4;
        *(float4*)&Vs[t * 64 + c4] = v4;
    }
    for (int idx = tid; idx < 27 * 64; idx += 256) { Rh[idx] = relh[idx]; Rw[idx] = relw[idx]; }
    __syncthreads();

    const int wid = tid >> 5, lane = tid & 31;

    for (int i = wid; i < NTOK; i += 8) {
        const int p = i / 14, qc = i % 14;
        const float2 q2 = *(const float2*)&Qs[i * 68 + 2 * lane];
        float acch[14], accw[14];
        #pragma unroll
        for (int r = 0; r < 14; r++) {
            const float2 rh2 = *(const float2*)&Rh[(p  + 13 - r) * 64 + 2 * lane];
            const float2 rw2 = *(const float2*)&Rw[(qc + 13 - r) * 64 + 2 * lane];
            acch[r] = q2.x * rh2.x + q2.y * rh2.y;
            accw[r] = q2.x * rw2.x + q2.y * rw2.y;
        }
        #pragma unroll
        for (int o = 16; o; o >>= 1) {
            #pragma unroll
            for (int r = 0; r < 14; r++) {
                acch[r] += __shfl_xor_sync(0xffffffffu, acch[r], o);
                accw[r] += __shfl_xor_sync(0xffffffffu, accw[r], o);
            }
        }
        if (lane == 0) {
            #pragma unroll
            for (int r = 0; r < 14; r++) { BHs[i*14+r] = acch[r]; BWs[i*14+r] = accw[r]; }
        }
    }
    __syncthreads();

    const float SCALE = 0.125f;
    float* P0 = Ps + wid * (2 * NTOK);
    float* P1 = P0 + NTOK;

    for (int i0 = wid * 2; i0 < NTOK; i0 += 16) {
        const int i1 = i0 + 1;
        const float* q0p = &Qs[i0 * 68];
        const float* q1p = &Qs[i1 * 68];
        float s0[7], s1[7];
        float mx0 = -1e30f, mx1 = -1e30f;
        #pragma unroll
        for (int jj = 0; jj < 7; jj++) {
            const int j = jj * 32 + lane;
            float a0 = -1e30f, a1 = -1e30f;
            if (j < NTOK) {
                const float* kr = &Ks[j * 68];
                float d0 = 0.f, d1 = 0.f;
                #pragma unroll
                for (int d = 0; d < 64; d += 4) {
                    float4 k4 = *(const float4*)(kr + d);
                    float4 qa = *(const float4*)(q0p + d);
                    float4 qb = *(const float4*)(q1p + d);
                    d0 += qa.x*k4.x + qa.y*k4.y + qa.z*k4.z + qa.w*k4.w;
                    d1 += qb.x*k4.x + qb.y*k4.y + qb.z*k4.z + qb.w*k4.w;
                }
                const int jp = j / 14, jq = j % 14;
                a0 = d0 * SCALE + BHs[i0*14+jp] + BWs[i0*14+jq];
                a1 = d1 * SCALE + BHs[i1*14+jp] + BWs[i1*14+jq];
            }
            s0[jj] = a0; s1[jj] = a1;
            mx0 = fmaxf(mx0, a0); mx1 = fmaxf(mx1, a1);
        }
        #pragma unroll
        for (int o = 16; o; o >>= 1) {
            mx0 = fmaxf(mx0, __shfl_xor_sync(0xffffffffu, mx0, o));
            mx1 = fmaxf(mx1, __shfl_xor_sync(0xffffffffu, mx1, o));
        }
        float sum0 = 0.f, sum1 = 0.f;
        #pragma unroll
        for (int jj = 0; jj < 7; jj++) {
            float e0 = __expf(s0[jj] - mx0);
            float e1 = __expf(s1[jj] - mx1);
            if (jj * 32 + lane >= NTOK) { e0 = 0.f; e1 = 0.f; }
            s0[jj] = e0; s1[jj] = e1;
            sum0 += e0; sum1 += e1;
        }
        #pragma unroll
        for (int o = 16; o; o >>= 1) {
            sum0 += __shfl_xor_sync(0xffffffffu, sum0, o);
            sum1 += __shfl_xor_sync(0xffffffffu, sum1, o);
        }
        const float r0 = 1.f / sum0, r1 = 1.f / sum1;
        #pragma unroll
        for (int jj = 0; jj < 7; jj++) {
            const int j = jj * 32 + lane;
            if (j < NTOK) { P0[j] = s0[jj] * r0; P1[j] = s1[jj] * r1; }
        }
        __syncwarp();
        float o00 = 0.f, o01 = 0.f, o10 = 0.f, o11 = 0.f;
        #pragma unroll 7
        for (int j4 = 0; j4 < 49; j4++) {
            const float4 p0 = *(const float4*)(P0 + j4 * 4);
            const float4 p1 = *(const float4*)(P1 + j4 * 4);
            const float* vb = &Vs[j4 * 4 * 64 + 2 * lane];
            const float2 v0 = *(const float2*)(vb);
            const float2 v1 = *(const float2*)(vb + 64);
            const float2 v2 = *(const float2*)(vb + 128);
            const float2 v3 = *(const float2*)(vb + 192);
            o00 += p0.x*v0.x + p0.y*v1.x + p0.z*v2.x + p0.w*v3.x;
            o01 += p0.x*v0.y + p0.y*v1.y + p0.z*v2.y + p0.w*v3.y;
            o10 += p1.x*v0.x + p1.y*v1.x + p1.z*v2.x + p1.w*v3.x;
            o11 += p1.x*v0.y + p1.y*v1.y + p1.z*v2.y + p1.w*v3.y;
        }
        const size_t r0o = (size_t)(w * NTOK + i0) * EMBED + h * HD + 2 * lane;
        const size_t r1o = (size_t)(w * NTOK + i1) * EMBED + h * HD + 2 * lane;
        __nv_bfloat162 Hh, Ll;
        split2(o00, Hh.x, Ll.x); split2(o01, Hh.y, Ll.y);
        *(__nv_bfloat162*)(aohi + r0o) = Hh; *(__nv_bfloat162*)(aolo + r0o) = Ll;
        split2(o10, Hh.x, Ll.x); split2(o11, Hh.y, Ll.y);
        *(__nv_bfloat162*)(aohi + r1o) = Hh; *(__nv_bfloat162*)(aolo + r1o) = Ll;
        __syncwarp();
    }
}

// ---------------------------------------------------------------------------
// kernel_launch
// ---------------------------------------------------------------------------
extern "C" void kernel_launch(void* const* d_in, const int* in_sizes, int n_in,
                              void* d_out, int out_size)
{
    const float* x      = (const float*)d_in[0];
    const float* g1     = (const float*)d_in[1];
    const float* beta1  = (const float*)d_in[2];
    const float* w_qkv  = (const float*)d_in[3];
    const float* b_qkv  = (const float*)d_in[4];
    const float* w_proj = (const float*)d_in[5];
    const float* b_proj = (const float*)d_in[6];
    const float* relh   = (const float*)d_in[7];
    const float* relw   = (const float*)d_in[8];
    const float* g2     = (const float*)d_in[9];
    const float* beta2  = (const float*)d_in[10];
    const float* w_fc1  = (const float*)d_in[11];
    const float* b_fc1  = (const float*)d_in[12];
    const float* w_fc2  = (const float*)d_in[13];
    const float* b_fc2  = (const float*)d_in[14];
    float* out = (float*)d_out;

    __nv_bfloat16 *hwin_h, *hwin_l, *attn_h, *attn_l, *h2_h, *h2_l, *ff_h, *ff_l;
    __nv_bfloat16 *wqkv_h, *wqkv_l, *wprj_h, *wprj_l, *wf1_h, *wf1_l, *wf2_h, *wf2_l;
    float *qkv, *x1;
    cudaGetSymbolAddress((void**)&hwin_h, g_hwin_hi);
    cudaGetSymbolAddress((void**)&hwin_l, g_hwin_lo);
    cudaGetSymbolAddress((void**)&qkv,    g_qkv);
    cudaGetSymbolAddress((void**)&attn_h, g_attn_hi);
    cudaGetSymbolAddress((void**)&attn_l, g_attn_lo);
    cudaGetSymbolAddress((void**)&x1,     g_x1);
    cudaGetSymbolAddress((void**)&h2_h,   g_h2_hi);
    cudaGetSymbolAddress((void**)&h2_l,   g_h2_lo);
    cudaGetSymbolAddress((void**)&ff_h,   g_ff_hi);
    cudaGetSymbolAddress((void**)&ff_l,   g_ff_lo);
    cudaGetSymbolAddress((void**)&wqkv_h, g_wqkv_hi);
    cudaGetSymbolAddress((void**)&wqkv_l, g_wqkv_lo);
    cudaGetSymbolAddress((void**)&wprj_h, g_wprj_hi);
    cudaGetSymbolAddress((void**)&wprj_l, g_wprj_lo);
    cudaGetSymbolAddress((void**)&wf1_h,  g_wfc1_hi);
    cudaGetSymbolAddress((void**)&wf1_l,  g_wfc1_lo);
    cudaGetSymbolAddress((void**)&wf2_h,  g_wfc2_hi);
    cudaGetSymbolAddress((void**)&wf2_l,  g_wfc2_lo);

    cudaFuncSetAttribute(attn_kernel, cudaFuncAttributeMaxDynamicSharedMemorySize, ATTN_SMEM_BYTES);
    cudaFuncSetAttribute(tgemm<0>, cudaFuncAttributeMaxDynamicSharedMemorySize, GSM_BYTES);
    cudaFuncSetAttribute(tgemm<1>, cudaFuncAttributeMaxDynamicSharedMemorySize, GSM_BYTES);
    cudaFuncSetAttribute(tgemm<2>, cudaFuncAttributeMaxDynamicSharedMemorySize, GSM_BYTES);
    cudaFuncSetAttribute(tgemm<3>, cudaFuncAttributeMaxDynamicSharedMemorySize, GSM_BYTES);

    // weight prep (transpose + bf16 split)
    wprep<<<dim3(QKVN/32, EMBED/32), 256>>>(w_qkv,  wqkv_h, wqkv_l, EMBED, QKVN);
    wprep<<<dim3(EMBED/32, EMBED/32), 256>>>(w_proj, wprj_h, wprj_l, EMBED, EMBED);
    wprep<<<dim3(FFDIM/32, EMBED/32), 256>>>(w_fc1,  wf1_h,  wf1_l,  EMBED, FFDIM);
    wprep<<<dim3(EMBED/32, FFDIM/32), 256>>>(w_fc2,  wf2_h,  wf2_l,  FFDIM, EMBED);

    // 1. LN1 + window partition
    ln1_part_kernel<<<M_WIN, 256>>>(x, g1, beta1, hwin_h, hwin_l);

    // 2. QKV projection
    tgemm<0><<<dim3(QKVN/128, (M_WIN + 127)/128), 256, GSM_BYTES>>>(
        hwin_h, hwin_l, wqkv_h, wqkv_l, b_qkv, qkv, nullptr, nullptr,
        M_WIN, QKVN, EMBED, nullptr);

    // 3. Window attention
    attn_kernel<<<NWIN * NHEAD, 256, ATTN_SMEM_BYTES>>>(qkv, relh, relw, attn_h, attn_l);

    // 4. proj + unpartition + residual
    tgemm<3><<<dim3(EMBED/128, (M_WIN + 127)/128), 256, GSM_BYTES>>>(
        attn_h, attn_l, wprj_h, wprj_l, b_proj, x1, nullptr, nullptr,
        M_WIN, EMBED, EMBED, x);

    // 5. LN2
    ln2_kernel<<<M_TOK, 256>>>(x1, g2, beta2, h2_h, h2_l);

    // 6. fc1 + GELU -> split bf16
    tgemm<1><<<dim3(FFDIM/128, M_TOK/128), 256, GSM_BYTES>>>(
        h2_h, h2_l, wf1_h, wf1_l, b_fc1, nullptr, ff_h, ff_l,
        M_TOK, FFDIM, EMBED, nullptr);

    // 7. fc2 + residual -> out
    tgemm<2><<<dim3(EMBED/128, M_TOK/128), 256, GSM_BYTES>>>(
        ff_h, ff_l, wf2_h, wf2_l, b_fc2, out, nullptr, nullptr,
        M_TOK, EMBED, FFDIM, x1);
}